// round 8
// baseline (speedup 1.0000x reference)
#include <cuda_runtime.h>
#include <cuda_fp16.h>
#include <cstdint>
#include <cstddef>

#define BB 128
#define SS 1024
#define II 512
#define HH 1024
#define GG 4096
#define NCTA2 128

// ---------------- device scratch (statics are the sanctioned no-alloc workaround) --------------
__device__ __half g_x_h[(size_t)BB * SS * II];        // x fp16, [B][S][I]
__device__ __half g_Wx_h[(size_t)GG * II];            // Wx fp16 [4H][I]
__device__ __half g_Wh_h[(size_t)GG * HH];            // Wh fp16 [4H][H]
__device__ float  g_bsum[GG];                         // bW + bU
__device__ __half g_xg[(size_t)SS * BB * GG];         // xg fp16, [S][B][4H]  (1 GiB)
__device__ __half g_h16[2][BB * HH];                  // ping-pong h (fp16)
__device__ float  g_h32[BB * HH];                     // final h (fp32) for head
__device__ unsigned g_bar_count;
__device__ unsigned g_bar_gen;

// ---------------- helpers ----------------
__device__ __forceinline__ uint32_t smem_u32(const void* p) {
    return (uint32_t)__cvta_generic_to_shared(p);
}
__device__ __forceinline__ void cp_async16(void* dst, const void* src) {
    // .cg: bypass L1. Needed for h (written by other SMs; L1 is per-SM incoherent).
    asm volatile("cp.async.cg.shared.global [%0], [%1], 16;\n" ::"r"(smem_u32(dst)), "l"(src));
}
__device__ __forceinline__ void cp_commit() { asm volatile("cp.async.commit_group;\n"); }
template <int N>
__device__ __forceinline__ void cp_wait() { asm volatile("cp.async.wait_group %0;\n" ::"n"(N)); }

__device__ __forceinline__ void ldsm_x4(uint32_t (&r)[4], const void* p) {
    asm volatile("ldmatrix.sync.aligned.m8n8.x4.shared.b16 {%0,%1,%2,%3}, [%4];\n"
                 : "=r"(r[0]), "=r"(r[1]), "=r"(r[2]), "=r"(r[3])
                 : "r"(smem_u32(p)));
}
__device__ __forceinline__ void mma16816(float (&d)[4], const uint32_t (&a)[4],
                                         uint32_t b0, uint32_t b1) {
    asm volatile("mma.sync.aligned.m16n8k16.row.col.f32.f16.f16.f32 "
                 "{%0,%1,%2,%3}, {%4,%5,%6,%7}, {%8,%9}, {%0,%1,%2,%3};\n"
                 : "+f"(d[0]), "+f"(d[1]), "+f"(d[2]), "+f"(d[3])
                 : "r"(a[0]), "r"(a[1]), "r"(a[2]), "r"(a[3]), "r"(b0), "r"(b1));
}
__device__ __forceinline__ float sigm(float x) { return 1.f / (1.f + expf(-x)); }

// Grid barrier: safe because all 128 CTAs are resident (1 CTA/SM forced by 180KB smem).
__device__ __forceinline__ void grid_barrier() {
    __threadfence();
    __syncthreads();
    if (threadIdx.x == 0) {
        unsigned g = *(volatile unsigned*)&g_bar_gen;   // snapshot BEFORE arriving
        unsigned old = atomicAdd(&g_bar_count, 1u);
        if (old == (unsigned)(NCTA2 - 1)) {
            atomicExch(&g_bar_count, 0u);
            __threadfence();
            atomicAdd(&g_bar_gen, 1u);                  // release
        } else {
            while (*(volatile unsigned*)&g_bar_gen == g) __nanosleep(64);
            __threadfence();                            // acquire
        }
    }
    __syncthreads();
}

// ---------------- conversion / init ----------------
__global__ void lstm_f2h(const float* __restrict__ src, int which, int n) {
    __half* dst = (which == 0) ? g_x_h : (which == 1) ? g_Wx_h : g_Wh_h;
    int stride = gridDim.x * blockDim.x;
    for (int i = blockIdx.x * blockDim.x + threadIdx.x; i < n; i += stride)
        dst[i] = __float2half(src[i]);
}

__global__ void lstm_prep(const float* __restrict__ bW, const float* __restrict__ bU) {
    int i = blockIdx.x * blockDim.x + threadIdx.x;   // grid covers 131072
    if (i < GG) g_bsum[i] = bW[i] + bU[i];
    if (i < BB * HH) {
        g_h16[0][i] = __float2half(0.f);
        g_h16[1][i] = __float2half(0.f);
    }
    if (i == 0) { g_bar_count = 0u; g_bar_gen = 0u; }
}

// ---------------- phase 1: xg = x @ Wx^T + bsum   [M=131072, N=4096, K=512] ----------------
// CTA tile 128x128, k-chunk 64, double-buffered cp.async; 8 warps as 4(M)x2(N), warp tile 32x64.
// smem rows padded to 72 halves (144B = 9*16B, conflict-free ldmatrix).
#define P1_SMEM (2 * 2 * 128 * 72 * 2) /* 73728 B */

__global__ void __launch_bounds__(256) lstm_xproj() {
    extern __shared__ __half sm1[];
    __half* As = sm1;                  // [2][128][72]
    __half* Bs = sm1 + 2 * 128 * 72;   // [2][128][72]
    const int tid = threadIdx.x;
    const int lane = tid & 31, wid = tid >> 5;
    const int wm = wid >> 1, wn = wid & 1;
    const int n0 = blockIdx.x * 128;
    const int sblk = blockIdx.y;       // s index; tile rows are b = 0..127

    float acc[2][8][4];
#pragma unroll
    for (int mi = 0; mi < 2; ++mi)
#pragma unroll
        for (int f = 0; f < 8; ++f)
#pragma unroll
            for (int u = 0; u < 4; ++u) acc[mi][f][u] = 0.f;

#define P1_LOAD(buf, kc)                                                           \
    {                                                                              \
        int k0_ = (kc) * 64;                                                       \
        _Pragma("unroll") for (int it = 0; it < 4; ++it) {                         \
            int task = tid + it * 256;                                             \
            int row = task >> 3, seg = task & 7;                                   \
            cp_async16(&As[(buf) * 9216 + row * 72 + seg * 8],                     \
                       g_x_h + ((size_t)row * SS + sblk) * II + k0_ + seg * 8);    \
            cp_async16(&Bs[(buf) * 9216 + row * 72 + seg * 8],                     \
                       g_Wx_h + (size_t)(n0 + row) * II + k0_ + seg * 8);          \
        }                                                                          \
    }

    P1_LOAD(0, 0);
    cp_commit();
#pragma unroll 1
    for (int kc = 0; kc < 8; ++kc) {
        int buf = kc & 1;
        if (kc < 7) { P1_LOAD(buf ^ 1, kc + 1); cp_commit(); cp_wait<1>(); }
        else        { cp_wait<0>(); }
        __syncthreads();
#pragma unroll
        for (int kk = 0; kk < 4; ++kk) {
            uint32_t a[2][4];
#pragma unroll
            for (int mi = 0; mi < 2; ++mi) {
                int row = wm * 32 + mi * 16 + (lane & 15);
                ldsm_x4(a[mi], &As[buf * 9216 + row * 72 + kk * 16 + (lane >> 4) * 8]);
            }
#pragma unroll
            for (int nj = 0; nj < 4; ++nj) {
                uint32_t b4[4];
                int row = wn * 64 + nj * 16 + (lane & 15);
                ldsm_x4(b4, &Bs[buf * 9216 + row * 72 + kk * 16 + (lane >> 4) * 8]);
#pragma unroll
                for (int mi = 0; mi < 2; ++mi) {
                    mma16816(acc[mi][nj * 2 + 0], a[mi], b4[0], b4[2]);
                    mma16816(acc[mi][nj * 2 + 1], a[mi], b4[1], b4[3]);
                }
            }
        }
        __syncthreads();
    }

    // epilogue: row m = sblk*128 + b; add bias; store fp16
    const int r = lane >> 2, c2 = (lane & 3) * 2;
    const size_t mbase = (size_t)sblk * 128;
#pragma unroll
    for (int mi = 0; mi < 2; ++mi) {
        int mrow = wm * 32 + mi * 16 + r;
#pragma unroll
        for (int f = 0; f < 8; ++f) {
            int col = n0 + wn * 64 + f * 8 + c2;
            float b0 = g_bsum[col], b1 = g_bsum[col + 1];
            __half2* p0 = (__half2*)(g_xg + (mbase + mrow) * (size_t)GG + col);
            *p0 = __floats2half2_rn(acc[mi][f][0] + b0, acc[mi][f][1] + b1);
            __half2* p1 = (__half2*)(g_xg + (mbase + mrow + 8) * (size_t)GG + col);
            *p1 = __floats2half2_rn(acc[mi][f][2] + b0, acc[mi][f][3] + b1);
        }
    }
}

// ---------------- phase 2: persistent LSTM recurrence ----------------
// 128 CTAs: ms = blk>>6 (B half, 64 rows), ns = blk&63 (16 h-cols -> 64 gate rows).
// SMEM: Whs 64x1032 halves (132096B) | Hs 2x64x136 halves (34816B) | Gs 64x68 floats (17408B)
#define WHS_STRIDE 1032
#define HCH_STRIDE 136
#define GS_STRIDE  68
#define P2_SMEM (132096 + 34816 + 17408) /* 184320 B */

__global__ void __launch_bounds__(256, 1) lstm_rec() {
    extern __shared__ unsigned char smraw[];
    __half* Whs = (__half*)smraw;
    __half* Hs  = (__half*)(smraw + 132096);
    float*  Gs  = (float*)(smraw + 132096 + 34816);
    const int tid = threadIdx.x;
    const int lane = tid & 31, wid = tid >> 5;
    const int wm = wid >> 2, wn = wid & 3;       // 2(M) x 4(N) warps
    const int ms = blockIdx.x >> 6;
    const int ns = blockIdx.x & 63;

    // Load resident Wh slice: smem row j -> gate (j>>4), h-col ns*16+(j&15)
#pragma unroll 4
    for (int it = 0; it < 32; ++it) {
        int task = tid + it * 256;
        int j = task >> 7, seg = task & 127;
        int grow = (j >> 4) * HH + ns * 16 + (j & 15);
        cp_async16(&Whs[j * WHS_STRIDE + seg * 8], g_Wh_h + (size_t)grow * HH + seg * 8);
    }
    cp_commit();
    cp_wait<0>();
    __syncthreads();

    float cst[4] = {0.f, 0.f, 0.f, 0.f};
    const int hc = tid & 15;
    const int brow0 = tid >> 4;   // 0..15 (+16k)

#define H_LOAD(buf, kc)                                                            \
    {                                                                              \
        _Pragma("unroll") for (int it = 0; it < 4; ++it) {                         \
            int task = tid + it * 256;                                             \
            int row = task >> 4, seg = task & 15;                                  \
            cp_async16(&Hs[(buf) * 64 * HCH_STRIDE + row * HCH_STRIDE + seg * 8],  \
                       hsrc + (size_t)row * HH + (kc) * 128 + seg * 8);            \
        }                                                                          \
    }

    for (int t = 0; t < SS; ++t) {
        const int par = t & 1;
        const __half* hsrc = g_h16[par] + (size_t)(ms * 64) * HH;

        // prefetch xg for this step (completes during the MMA loop)
        __half xh[4][4];
        const __half* xgp = g_xg + ((size_t)t * BB + ms * 64) * GG + ns * 16 + hc;
#pragma unroll
        for (int k = 0; k < 4; ++k) {
            int b = brow0 + k * 16;
#pragma unroll
            for (int g = 0; g < 4; ++g) xh[k][g] = xgp[(size_t)b * GG + g * HH];
        }

        float acc[2][2][4];
#pragma unroll
        for (int mi = 0; mi < 2; ++mi)
#pragma unroll
            for (int nh = 0; nh < 2; ++nh)
#pragma unroll
                for (int u = 0; u < 4; ++u) acc[mi][nh][u] = 0.f;

        H_LOAD(0, 0);
        cp_commit();
#pragma unroll 1
        for (int kc = 0; kc < 8; ++kc) {
            int buf = kc & 1;
            if (kc < 7) { H_LOAD(buf ^ 1, kc + 1); cp_commit(); cp_wait<1>(); }
            else        { cp_wait<0>(); }
            __syncthreads();
#pragma unroll
            for (int kk = 0; kk < 8; ++kk) {
                uint32_t a[2][4];
#pragma unroll
                for (int mi = 0; mi < 2; ++mi)
                    ldsm_x4(a[mi], &Hs[buf * 64 * HCH_STRIDE +
                                       (wm * 32 + mi * 16 + (lane & 15)) * HCH_STRIDE +
                                       kk * 16 + (lane >> 4) * 8]);
                uint32_t b4[4];
                ldsm_x4(b4, &Whs[(wn * 16 + (lane & 15)) * WHS_STRIDE +
                                 kc * 128 + kk * 16 + (lane >> 4) * 8]);
#pragma unroll
                for (int mi = 0; mi < 2; ++mi) {
                    mma16816(acc[mi][0], a[mi], b4[0], b4[2]);
                    mma16816(acc[mi][1], a[mi], b4[1], b4[3]);
                }
            }
            __syncthreads();
        }

        // store gate tile to smem (transpose to per-(b,hc) access)
        {
            int r = lane >> 2, c2 = (lane & 3) * 2;
#pragma unroll
            for (int mi = 0; mi < 2; ++mi)
#pragma unroll
                for (int nh = 0; nh < 2; ++nh) {
                    int col = wn * 16 + nh * 8 + c2;
                    int row = wm * 32 + mi * 16 + r;
                    Gs[row * GS_STRIDE + col]           = acc[mi][nh][0];
                    Gs[row * GS_STRIDE + col + 1]       = acc[mi][nh][1];
                    Gs[(row + 8) * GS_STRIDE + col]     = acc[mi][nh][2];
                    Gs[(row + 8) * GS_STRIDE + col + 1] = acc[mi][nh][3];
                }
        }
        __syncthreads();

        // elementwise update; c in registers; write h fp16 to other buffer
        __half* hdst = g_h16[par ^ 1] + (size_t)(ms * 64) * HH + ns * 16;
#pragma unroll
        for (int k = 0; k < 4; ++k) {
            int b = brow0 + k * 16;
            float f  = Gs[b * GS_STRIDE + hc]      + __half2float(xh[k][0]);
            float i_ = Gs[b * GS_STRIDE + 16 + hc] + __half2float(xh[k][1]);
            float g  = Gs[b * GS_STRIDE + 32 + hc] + __half2float(xh[k][2]);
            float o  = Gs[b * GS_STRIDE + 48 + hc] + __half2float(xh[k][3]);
            cst[k] = sigm(f) * cst[k] + sigm(i_) * tanhf(g);
            float h = sigm(o) * tanhf(cst[k]);
            hdst[(size_t)b * HH + hc] = __float2half(h);
            if (t == SS - 1) g_h32[(size_t)(ms * 64 + b) * HH + ns * 16 + hc] = h;
        }
        grid_barrier();
    }
}

// ---------------- head: out = hT @ fc_w^T + fc_b  [128x128, K=1024] ----------------
__global__ void lstm_head(const float* __restrict__ fc_w, const float* __restrict__ fc_b,
                          float* __restrict__ out) {
    __shared__ float hrow[HH];
    int b = blockIdx.x;
    for (int i = threadIdx.x; i < HH; i += 128) hrow[i] = g_h32[(size_t)b * HH + i];
    __syncthreads();
    int o = threadIdx.x;
    const float4* wp = (const float4*)(fc_w + (size_t)o * HH);
    float s = 0.f;
#pragma unroll 4
    for (int i = 0; i < HH / 4; ++i) {
        float4 w = wp[i];
        s += w.x * hrow[i * 4] + w.y * hrow[i * 4 + 1] + w.z * hrow[i * 4 + 2] + w.w * hrow[i * 4 + 3];
    }
    out[b * 128 + o] = s + fc_b[o];
}

// ---------------- launch ----------------
extern "C" void kernel_launch(void* const* d_in, const int* in_sizes, int n_in,
                              void* d_out, int out_size) {
    const float* x    = (const float*)d_in[0];
    const float* Wx   = (const float*)d_in[1];
    const float* bW   = (const float*)d_in[2];
    const float* Wh   = (const float*)d_in[3];
    const float* bU   = (const float*)d_in[4];
    const float* fc_w = (const float*)d_in[5];
    const float* fc_b = (const float*)d_in[6];
    float* out = (float*)d_out;

    cudaFuncSetAttribute(lstm_xproj, cudaFuncAttributeMaxDynamicSharedMemorySize, P1_SMEM);
    cudaFuncSetAttribute(lstm_rec,   cudaFuncAttributeMaxDynamicSharedMemorySize, P2_SMEM);

    lstm_f2h<<<4096, 256>>>(x,  0, BB * SS * II);
    lstm_f2h<<<1024, 256>>>(Wx, 1, GG * II);
    lstm_f2h<<<1024, 256>>>(Wh, 2, GG * HH);
    lstm_prep<<<512, 256>>>(bW, bU);
    lstm_xproj<<<dim3(32, 1024), 256, P1_SMEM>>>();
    lstm_rec<<<NCTA2, 256, P2_SMEM>>>();
    lstm_head<<<128, 128>>>(fc_w, fc_b, out);
}

// round 9
// speedup vs baseline: 1.0550x; 1.0550x over previous
#include <cuda_runtime.h>
#include <cuda_fp16.h>
#include <cstdint>
#include <cstddef>

#define BB 128
#define SS 1024
#define II 512
#define HH 1024
#define GG 4096
#define NCTA2 128

// ---------------- device scratch (statics are the sanctioned no-alloc workaround) --------------
__device__ __half g_x_h[(size_t)BB * SS * II];        // x fp16, [B][S][I]
__device__ __half g_Wx_h[(size_t)GG * II];            // Wx fp16 [4H][I]
__device__ __half g_Wh_h[(size_t)GG * HH];            // Wh fp16 [4H][H]
__device__ float  g_bsum[GG];                         // bW + bU
__device__ __half g_xg[(size_t)SS * BB * GG];         // xg fp16, [S][B][4H]  (1 GiB)
__device__ __half g_h16[2][BB * HH];                  // ping-pong h (fp16)
__device__ float  g_h32[BB * HH];                     // final h (fp32) for head
__device__ unsigned g_bar_count;
__device__ unsigned g_bar_gen;

// ---------------- helpers ----------------
__device__ __forceinline__ uint32_t smem_u32(const void* p) {
    return (uint32_t)__cvta_generic_to_shared(p);
}
__device__ __forceinline__ void cp_async16(void* dst, const void* src) {
    // .cg: bypass L1. Needed for h (written by other SMs; L1 is per-SM incoherent).
    asm volatile("cp.async.cg.shared.global [%0], [%1], 16;\n" ::"r"(smem_u32(dst)), "l"(src));
}
__device__ __forceinline__ void cp_commit() { asm volatile("cp.async.commit_group;\n"); }
template <int N>
__device__ __forceinline__ void cp_wait() { asm volatile("cp.async.wait_group %0;\n" ::"n"(N)); }

__device__ __forceinline__ void ldsm_x4(uint32_t (&r)[4], const void* p) {
    asm volatile("ldmatrix.sync.aligned.m8n8.x4.shared.b16 {%0,%1,%2,%3}, [%4];\n"
                 : "=r"(r[0]), "=r"(r[1]), "=r"(r[2]), "=r"(r[3])
                 : "r"(smem_u32(p)));
}
__device__ __forceinline__ void mma16816(float (&d)[4], const uint32_t (&a)[4],
                                         uint32_t b0, uint32_t b1) {
    asm volatile("mma.sync.aligned.m16n8k16.row.col.f32.f16.f16.f32 "
                 "{%0,%1,%2,%3}, {%4,%5,%6,%7}, {%8,%9}, {%0,%1,%2,%3};\n"
                 : "+f"(d[0]), "+f"(d[1]), "+f"(d[2]), "+f"(d[3])
                 : "r"(a[0]), "r"(a[1]), "r"(a[2]), "r"(a[3]), "r"(b0), "r"(b1));
}
// MUFU-only activations (rel err ~1e-6; no impact at our 3.3e-4 error level)
__device__ __forceinline__ float sigm(float x) {
    return __fdividef(1.f, 1.f + __expf(-x));
}
__device__ __forceinline__ float tanh_fast(float x) {
    return 1.f - __fdividef(2.f, __expf(2.f * x) + 1.f);
}

// Grid barrier: safe because all 128 CTAs are resident (1 CTA/SM forced by ~197KB smem).
__device__ __forceinline__ void grid_barrier() {
    __threadfence();
    __syncthreads();
    if (threadIdx.x == 0) {
        unsigned g = *(volatile unsigned*)&g_bar_gen;   // snapshot BEFORE arriving
        unsigned old = atomicAdd(&g_bar_count, 1u);
        if (old == (unsigned)(NCTA2 - 1)) {
            *(volatile unsigned*)&g_bar_count = 0u;
            __threadfence();
            atomicAdd(&g_bar_gen, 1u);                  // release
        } else {
            unsigned cur;
            do {
                asm volatile("ld.acquire.gpu.b32 %0, [%1];"
                             : "=r"(cur) : "l"(&g_bar_gen) : "memory");
            } while (cur == g);
        }
    }
    __syncthreads();
}

// ---------------- init kernels (2 launches so lstm_rec lands at launch #4 for ncu) -------------
__global__ void lstm_prep_w(const float* __restrict__ Wx, const float* __restrict__ Wh,
                            const float* __restrict__ bW, const float* __restrict__ bU) {
    int stride = gridDim.x * blockDim.x;
    int i0 = blockIdx.x * blockDim.x + threadIdx.x;
    for (int i = i0; i < GG * HH; i += stride) g_Wh_h[i] = __float2half(Wh[i]);
    for (int i = i0; i < GG * II; i += stride) g_Wx_h[i] = __float2half(Wx[i]);
    if (i0 < GG) g_bsum[i0] = bW[i0] + bU[i0];
    if (i0 < BB * HH) {
        g_h16[0][i0] = __float2half(0.f);
        g_h16[1][i0] = __float2half(0.f);
    }
    if (i0 == 0) { g_bar_count = 0u; g_bar_gen = 0u; }
}

__global__ void lstm_prep_x(const float* __restrict__ x) {
    int stride = gridDim.x * blockDim.x;
    for (int i = blockIdx.x * blockDim.x + threadIdx.x; i < BB * SS * II; i += stride)
        g_x_h[i] = __float2half(x[i]);
}

// ---------------- phase 1: xg = x @ Wx^T + bsum   [M=131072, N=4096, K=512] ----------------
// CTA tile 128x128, k-chunk 64, double-buffered cp.async; 8 warps as 4(M)x2(N), warp tile 32x64.
// smem rows padded to 72 halves (144B = 9*16B, conflict-free ldmatrix).
#define P1_SMEM (2 * 2 * 128 * 72 * 2) /* 73728 B */

__global__ void __launch_bounds__(256) lstm_xproj() {
    extern __shared__ __half sm1[];
    __half* As = sm1;                  // [2][128][72]
    __half* Bs = sm1 + 2 * 128 * 72;   // [2][128][72]
    const int tid = threadIdx.x;
    const int lane = tid & 31, wid = tid >> 5;
    const int wm = wid >> 1, wn = wid & 1;
    const int n0 = blockIdx.x * 128;
    const int sblk = blockIdx.y;       // s index; tile rows are b = 0..127

    float acc[2][8][4];
#pragma unroll
    for (int mi = 0; mi < 2; ++mi)
#pragma unroll
        for (int f = 0; f < 8; ++f)
#pragma unroll
            for (int u = 0; u < 4; ++u) acc[mi][f][u] = 0.f;

#define P1_LOAD(buf, kc)                                                           \
    {                                                                              \
        int k0_ = (kc) * 64;                                                       \
        _Pragma("unroll") for (int it = 0; it < 4; ++it) {                         \
            int task = tid + it * 256;                                             \
            int row = task >> 3, seg = task & 7;                                   \
            cp_async16(&As[(buf) * 9216 + row * 72 + seg * 8],                     \
                       g_x_h + ((size_t)row * SS + sblk) * II + k0_ + seg * 8);    \
            cp_async16(&Bs[(buf) * 9216 + row * 72 + seg * 8],                     \
                       g_Wx_h + (size_t)(n0 + row) * II + k0_ + seg * 8);          \
        }                                                                          \
    }

    P1_LOAD(0, 0);
    cp_commit();
#pragma unroll 1
    for (int kc = 0; kc < 8; ++kc) {
        int buf = kc & 1;
        if (kc < 7) { P1_LOAD(buf ^ 1, kc + 1); cp_commit(); cp_wait<1>(); }
        else        { cp_wait<0>(); }
        __syncthreads();
#pragma unroll
        for (int kk = 0; kk < 4; ++kk) {
            uint32_t a[2][4];
#pragma unroll
            for (int mi = 0; mi < 2; ++mi) {
                int row = wm * 32 + mi * 16 + (lane & 15);
                ldsm_x4(a[mi], &As[buf * 9216 + row * 72 + kk * 16 + (lane >> 4) * 8]);
            }
#pragma unroll
            for (int nj = 0; nj < 4; ++nj) {
                uint32_t b4[4];
                int row = wn * 64 + nj * 16 + (lane & 15);
                ldsm_x4(b4, &Bs[buf * 9216 + row * 72 + kk * 16 + (lane >> 4) * 8]);
#pragma unroll
                for (int mi = 0; mi < 2; ++mi) {
                    mma16816(acc[mi][nj * 2 + 0], a[mi], b4[0], b4[2]);
                    mma16816(acc[mi][nj * 2 + 1], a[mi], b4[1], b4[3]);
                }
            }
        }
        __syncthreads();
    }

    // epilogue: row m = sblk*128 + b; add bias; store fp16
    const int r = lane >> 2, c2 = (lane & 3) * 2;
    const size_t mbase = (size_t)sblk * 128;
#pragma unroll
    for (int mi = 0; mi < 2; ++mi) {
        int mrow = wm * 32 + mi * 16 + r;
#pragma unroll
        for (int f = 0; f < 8; ++f) {
            int col = n0 + wn * 64 + f * 8 + c2;
            float b0 = g_bsum[col], b1 = g_bsum[col + 1];
            __half2* p0 = (__half2*)(g_xg + (mbase + mrow) * (size_t)GG + col);
            *p0 = __floats2half2_rn(acc[mi][f][0] + b0, acc[mi][f][1] + b1);
            __half2* p1 = (__half2*)(g_xg + (mbase + mrow + 8) * (size_t)GG + col);
            *p1 = __floats2half2_rn(acc[mi][f][2] + b0, acc[mi][f][3] + b1);
        }
    }
}

// ---------------- phase 2: persistent LSTM recurrence ----------------
// 128 CTAs: ms = blk>>6 (B half, 64 rows), ns = blk&63 (16 h-cols -> 64 gate rows).
// SMEM: Whs 64x1032 halves (132096B) | Hs 4 buffers x 64x136 halves (17408B each).
// The fp32 gate-transpose buffer Gs ALIASES Hs buf0 (free after the MMA loop;
// reuse distance of buf0 is chunk 4, all threads are past chunk 6 when Gs is written).
#define WHS_STRIDE 1032
#define HCH_STRIDE 136
#define GS_STRIDE  68
#define HBUF_BYTES (64 * HCH_STRIDE * 2) /* 17408 */
#define P2_SMEM (132096 + 4 * HBUF_BYTES) /* 201728 B -> 1 CTA/SM */

__global__ void __launch_bounds__(256, 1) lstm_rec() {
    extern __shared__ unsigned char smraw[];
    __half* Whs = (__half*)smraw;
    __half* Hs  = (__half*)(smraw + 132096);
    float*  Gs  = (float*)(smraw + 132096);      // aliases Hs buf0
    const int tid = threadIdx.x;
    const int lane = tid & 31, wid = tid >> 5;
    const int wm = wid >> 2, wn = wid & 3;       // 2(M) x 4(N) warps
    const int ms = blockIdx.x >> 6;
    const int ns = blockIdx.x & 63;

    // Load resident Wh slice: smem row j -> gate (j>>4), h-col ns*16+(j&15)
#pragma unroll 4
    for (int it = 0; it < 32; ++it) {
        int task = tid + it * 256;
        int j = task >> 7, seg = task & 127;
        int grow = (j >> 4) * HH + ns * 16 + (j & 15);
        cp_async16(&Whs[j * WHS_STRIDE + seg * 8], g_Wh_h + (size_t)grow * HH + seg * 8);
    }
    cp_commit();
    cp_wait<0>();
    __syncthreads();

    float cst[4] = {0.f, 0.f, 0.f, 0.f};
    const int hc = tid & 15;
    const int brow0 = tid >> 4;   // 0..15 (+16k)

#define H_LOAD(buf, kc)                                                            \
    {                                                                              \
        _Pragma("unroll") for (int it = 0; it < 4; ++it) {                         \
            int task = tid + it * 256;                                             \
            int row = task >> 4, seg = task & 15;                                  \
            cp_async16(&Hs[(buf) * (64 * HCH_STRIDE) + row * HCH_STRIDE + seg * 8],\
                       hsrc + (size_t)row * HH + (kc) * 128 + seg * 8);            \
        }                                                                          \
    }

    for (int t = 0; t < SS; ++t) {
        const int par = t & 1;
        const __half* hsrc = g_h16[par] + (size_t)(ms * 64) * HH;

        // prefetch xg for this step (DRAM latency hidden under the MMA loop)
        __half xh[4][4];
        const __half* xgp = g_xg + ((size_t)t * BB + ms * 64) * GG + ns * 16 + hc;
#pragma unroll
        for (int k = 0; k < 4; ++k) {
            int b = brow0 + k * 16;
#pragma unroll
            for (int g = 0; g < 4; ++g) xh[k][g] = xgp[(size_t)b * GG + g * HH];
        }

        float acc[2][2][4];
#pragma unroll
        for (int mi = 0; mi < 2; ++mi)
#pragma unroll
            for (int nh = 0; nh < 2; ++nh)
#pragma unroll
                for (int u = 0; u < 4; ++u) acc[mi][nh][u] = 0.f;

        // 4-deep cp.async pipeline over the 8 k-chunks (prefetch 3 ahead)
        H_LOAD(0, 0); cp_commit();
        H_LOAD(1, 1); cp_commit();
        H_LOAD(2, 2); cp_commit();
#pragma unroll 1
        for (int kc = 0; kc < 8; ++kc) {
            if (kc < 6)      cp_wait<2>();
            else if (kc == 6) cp_wait<1>();
            else             cp_wait<0>();
            __syncthreads();
            if (kc < 5) { H_LOAD((kc + 3) & 3, kc + 3); cp_commit(); }
            const int buf = kc & 3;
#pragma unroll
            for (int kk = 0; kk < 8; ++kk) {
                uint32_t a[2][4];
#pragma unroll
                for (int mi = 0; mi < 2; ++mi)
                    ldsm_x4(a[mi], &Hs[buf * (64 * HCH_STRIDE) +
                                       (wm * 32 + mi * 16 + (lane & 15)) * HCH_STRIDE +
                                       kk * 16 + (lane >> 4) * 8]);
                uint32_t b4[4];
                ldsm_x4(b4, &Whs[(wn * 16 + (lane & 15)) * WHS_STRIDE +
                                 kc * 128 + kk * 16 + (lane >> 4) * 8]);
#pragma unroll
                for (int mi = 0; mi < 2; ++mi) {
                    mma16816(acc[mi][0], a[mi], b4[0], b4[2]);
                    mma16816(acc[mi][1], a[mi], b4[1], b4[3]);
                }
            }
        }

        // store gate tile to smem (transpose to per-(b,hc) access); Gs aliases Hs buf0
        {
            int r = lane >> 2, c2 = (lane & 3) * 2;
#pragma unroll
            for (int mi = 0; mi < 2; ++mi)
#pragma unroll
                for (int nh = 0; nh < 2; ++nh) {
                    int col = wn * 16 + nh * 8 + c2;
                    int row = wm * 32 + mi * 16 + r;
                    Gs[row * GS_STRIDE + col]           = acc[mi][nh][0];
                    Gs[row * GS_STRIDE + col + 1]       = acc[mi][nh][1];
                    Gs[(row + 8) * GS_STRIDE + col]     = acc[mi][nh][2];
                    Gs[(row + 8) * GS_STRIDE + col + 1] = acc[mi][nh][3];
                }
        }
        __syncthreads();

        // elementwise update; c in registers; write h fp16 to other buffer
        __half* hdst = g_h16[par ^ 1] + (size_t)(ms * 64) * HH + ns * 16;
#pragma unroll
        for (int k = 0; k < 4; ++k) {
            int b = brow0 + k * 16;
            float f  = Gs[b * GS_STRIDE + hc]      + __half2float(xh[k][0]);
            float i_ = Gs[b * GS_STRIDE + 16 + hc] + __half2float(xh[k][1]);
            float g  = Gs[b * GS_STRIDE + 32 + hc] + __half2float(xh[k][2]);
            float o  = Gs[b * GS_STRIDE + 48 + hc] + __half2float(xh[k][3]);
            cst[k] = sigm(f) * cst[k] + sigm(i_) * tanh_fast(g);
            float h = sigm(o) * tanh_fast(cst[k]);
            hdst[(size_t)b * HH + hc] = __float2half(h);
            if (t == SS - 1) g_h32[(size_t)(ms * 64 + b) * HH + ns * 16 + hc] = h;
        }
        grid_barrier();
    }
}

// ---------------- head: out = hT @ fc_w^T + fc_b  [128x128, K=1024] ----------------
__global__ void lstm_head(const float* __restrict__ fc_w, const float* __restrict__ fc_b,
                          float* __restrict__ out) {
    __shared__ float hrow[HH];
    int b = blockIdx.x;
    for (int i = threadIdx.x; i < HH; i += 128) hrow[i] = g_h32[(size_t)b * HH + i];
    __syncthreads();
    int o = threadIdx.x;
    const float4* wp = (const float4*)(fc_w + (size_t)o * HH);
    float s = 0.f;
#pragma unroll 4
    for (int i = 0; i < HH / 4; ++i) {
        float4 w = wp[i];
        s += w.x * hrow[i * 4] + w.y * hrow[i * 4 + 1] + w.z * hrow[i * 4 + 2] + w.w * hrow[i * 4 + 3];
    }
    out[b * 128 + o] = s + fc_b[o];
}

// ---------------- launch (5 launches; lstm_rec is #4 -> captured by ncu -s 5 -c 1) -------------
extern "C" void kernel_launch(void* const* d_in, const int* in_sizes, int n_in,
                              void* d_out, int out_size) {
    const float* x    = (const float*)d_in[0];
    const float* Wx   = (const float*)d_in[1];
    const float* bW   = (const float*)d_in[2];
    const float* Wh   = (const float*)d_in[3];
    const float* bU   = (const float*)d_in[4];
    const float* fc_w = (const float*)d_in[5];
    const float* fc_b = (const float*)d_in[6];
    float* out = (float*)d_out;

    cudaFuncSetAttribute(lstm_xproj, cudaFuncAttributeMaxDynamicSharedMemorySize, P1_SMEM);
    cudaFuncSetAttribute(lstm_rec,   cudaFuncAttributeMaxDynamicSharedMemorySize, P2_SMEM);

    lstm_prep_w<<<2048, 256>>>(Wx, Wh, bW, bU);
    lstm_prep_x<<<4096, 256>>>(x);
    lstm_xproj<<<dim3(32, 1024), 256, P1_SMEM>>>();
    lstm_rec<<<NCTA2, 256, P2_SMEM>>>();
    lstm_head<<<128, 128>>>(fc_w, fc_b, out);
}

// round 10
// speedup vs baseline: 1.0551x; 1.0001x over previous
#include <cuda_runtime.h>
#include <cuda_fp16.h>
#include <cstdint>
#include <cstddef>

#define BB 128
#define SS 1024
#define II 512
#define HH 1024
#define GG 4096
#define NCTA2 128

// ---------------- device scratch (statics are the sanctioned no-alloc workaround) --------------
__device__ __half g_x_h[(size_t)BB * SS * II];        // x fp16, [B][S][I]
__device__ __half g_Wx_h[(size_t)GG * II];            // Wx fp16 [4H][I]
__device__ __half g_Wh_h[(size_t)GG * HH];            // Wh fp16 [4H][H]
__device__ float  g_bsum[GG];                         // bW + bU
__device__ __half g_xg[(size_t)SS * BB * GG];         // xg fp16, [S][B][4H]  (1 GiB)
__device__ __half g_h16[2][BB * HH];                  // ping-pong h (fp16)
__device__ float  g_h32[BB * HH];                     // final h (fp32) for head
__device__ unsigned g_bar_count;
__device__ unsigned g_bar_gen;

// ---------------- helpers ----------------
__device__ __forceinline__ uint32_t smem_u32(const void* p) {
    return (uint32_t)__cvta_generic_to_shared(p);
}
__device__ __forceinline__ void cp_async16(void* dst, const void* src) {
    // .cg: bypass L1. Needed for h (written by other SMs; L1 is per-SM incoherent).
    asm volatile("cp.async.cg.shared.global [%0], [%1], 16;\n" ::"r"(smem_u32(dst)), "l"(src));
}
__device__ __forceinline__ void cp_commit() { asm volatile("cp.async.commit_group;\n"); }
template <int N>
__device__ __forceinline__ void cp_wait() { asm volatile("cp.async.wait_group %0;\n" ::"n"(N)); }

__device__ __forceinline__ void ldsm_x4(uint32_t (&r)[4], const void* p) {
    asm volatile("ldmatrix.sync.aligned.m8n8.x4.shared.b16 {%0,%1,%2,%3}, [%4];\n"
                 : "=r"(r[0]), "=r"(r[1]), "=r"(r[2]), "=r"(r[3])
                 : "r"(smem_u32(p)));
}
__device__ __forceinline__ void mma16816(float (&d)[4], const uint32_t (&a)[4],
                                         uint32_t b0, uint32_t b1) {
    asm volatile("mma.sync.aligned.m16n8k16.row.col.f32.f16.f16.f32 "
                 "{%0,%1,%2,%3}, {%4,%5,%6,%7}, {%8,%9}, {%0,%1,%2,%3};\n"
                 : "+f"(d[0]), "+f"(d[1]), "+f"(d[2]), "+f"(d[3])
                 : "r"(a[0]), "r"(a[1]), "r"(a[2]), "r"(a[3]), "r"(b0), "r"(b1));
}
// MUFU-only activations (rel err ~1e-6; no impact at our 3.3e-4 error level)
__device__ __forceinline__ float sigm(float x) {
    return __fdividef(1.f, 1.f + __expf(-x));
}
__device__ __forceinline__ float tanh_fast(float x) {
    return 1.f - __fdividef(2.f, __expf(2.f * x) + 1.f);
}

// Grid barrier: safe because all 128 CTAs are resident (1 CTA/SM forced by ~197KB smem).
__device__ __forceinline__ void grid_barrier() {
    __threadfence();
    __syncthreads();
    if (threadIdx.x == 0) {
        unsigned g = *(volatile unsigned*)&g_bar_gen;   // snapshot BEFORE arriving
        unsigned old = atomicAdd(&g_bar_count, 1u);
        if (old == (unsigned)(NCTA2 - 1)) {
            *(volatile unsigned*)&g_bar_count = 0u;
            __threadfence();
            atomicAdd(&g_bar_gen, 1u);                  // release
        } else {
            unsigned cur;
            do {
                asm volatile("ld.acquire.gpu.b32 %0, [%1];"
                             : "=r"(cur) : "l"(&g_bar_gen) : "memory");
            } while (cur == g);
        }
    }
    __syncthreads();
}

// ---------------- init kernels (2 launches so lstm_rec lands at launch #4 for ncu) -------------
__global__ void lstm_prep_w(const float* __restrict__ Wx, const float* __restrict__ Wh,
                            const float* __restrict__ bW, const float* __restrict__ bU) {
    int stride = gridDim.x * blockDim.x;
    int i0 = blockIdx.x * blockDim.x + threadIdx.x;
    for (int i = i0; i < GG * HH; i += stride) g_Wh_h[i] = __float2half(Wh[i]);
    for (int i = i0; i < GG * II; i += stride) g_Wx_h[i] = __float2half(Wx[i]);
    if (i0 < GG) g_bsum[i0] = bW[i0] + bU[i0];
    if (i0 < BB * HH) {
        g_h16[0][i0] = __float2half(0.f);
        g_h16[1][i0] = __float2half(0.f);
    }
    if (i0 == 0) { g_bar_count = 0u; g_bar_gen = 0u; }
}

__global__ void lstm_prep_x(const float* __restrict__ x) {
    int stride = gridDim.x * blockDim.x;
    for (int i = blockIdx.x * blockDim.x + threadIdx.x; i < BB * SS * II; i += stride)
        g_x_h[i] = __float2half(x[i]);
}

// ---------------- phase 1: xg = x @ Wx^T + bsum   [M=131072, N=4096, K=512] ----------------
// CTA tile 128x128, k-chunk 64, double-buffered cp.async; 8 warps as 4(M)x2(N), warp tile 32x64.
// smem rows padded to 72 halves (144B = 9*16B, conflict-free ldmatrix).
#define P1_SMEM (2 * 2 * 128 * 72 * 2) /* 73728 B */

__global__ void __launch_bounds__(256) lstm_xproj() {
    extern __shared__ __half sm1[];
    __half* As = sm1;                  // [2][128][72]
    __half* Bs = sm1 + 2 * 128 * 72;   // [2][128][72]
    const int tid = threadIdx.x;
    const int lane = tid & 31, wid = tid >> 5;
    const int wm = wid >> 1, wn = wid & 1;
    const int n0 = blockIdx.x * 128;
    const int sblk = blockIdx.y;       // s index; tile rows are b = 0..127

    float acc[2][8][4];
#pragma unroll
    for (int mi = 0; mi < 2; ++mi)
#pragma unroll
        for (int f = 0; f < 8; ++f)
#pragma unroll
            for (int u = 0; u < 4; ++u) acc[mi][f][u] = 0.f;

#define P1_LOAD(buf, kc)                                                           \
    {                                                                              \
        int k0_ = (kc) * 64;                                                       \
        _Pragma("unroll") for (int it = 0; it < 4; ++it) {                         \
            int task = tid + it * 256;                                             \
            int row = task >> 3, seg = task & 7;                                   \
            cp_async16(&As[(buf) * 9216 + row * 72 + seg * 8],                     \
                       g_x_h + ((size_t)row * SS + sblk) * II + k0_ + seg * 8);    \
            cp_async16(&Bs[(buf) * 9216 + row * 72 + seg * 8],                     \
                       g_Wx_h + (size_t)(n0 + row) * II + k0_ + seg * 8);          \
        }                                                                          \
    }

    P1_LOAD(0, 0);
    cp_commit();
#pragma unroll 1
    for (int kc = 0; kc < 8; ++kc) {
        int buf = kc & 1;
        if (kc < 7) { P1_LOAD(buf ^ 1, kc + 1); cp_commit(); cp_wait<1>(); }
        else        { cp_wait<0>(); }
        __syncthreads();
#pragma unroll
        for (int kk = 0; kk < 4; ++kk) {
            uint32_t a[2][4];
#pragma unroll
            for (int mi = 0; mi < 2; ++mi) {
                int row = wm * 32 + mi * 16 + (lane & 15);
                ldsm_x4(a[mi], &As[buf * 9216 + row * 72 + kk * 16 + (lane >> 4) * 8]);
            }
#pragma unroll
            for (int nj = 0; nj < 4; ++nj) {
                uint32_t b4[4];
                int row = wn * 64 + nj * 16 + (lane & 15);
                ldsm_x4(b4, &Bs[buf * 9216 + row * 72 + kk * 16 + (lane >> 4) * 8]);
#pragma unroll
                for (int mi = 0; mi < 2; ++mi) {
                    mma16816(acc[mi][nj * 2 + 0], a[mi], b4[0], b4[2]);
                    mma16816(acc[mi][nj * 2 + 1], a[mi], b4[1], b4[3]);
                }
            }
        }
        __syncthreads();
    }

    // epilogue: row m = sblk*128 + b; add bias; store fp16
    const int r = lane >> 2, c2 = (lane & 3) * 2;
    const size_t mbase = (size_t)sblk * 128;
#pragma unroll
    for (int mi = 0; mi < 2; ++mi) {
        int mrow = wm * 32 + mi * 16 + r;
#pragma unroll
        for (int f = 0; f < 8; ++f) {
            int col = n0 + wn * 64 + f * 8 + c2;
            float b0 = g_bsum[col], b1 = g_bsum[col + 1];
            __half2* p0 = (__half2*)(g_xg + (mbase + mrow) * (size_t)GG + col);
            *p0 = __floats2half2_rn(acc[mi][f][0] + b0, acc[mi][f][1] + b1);
            __half2* p1 = (__half2*)(g_xg + (mbase + mrow + 8) * (size_t)GG + col);
            *p1 = __floats2half2_rn(acc[mi][f][2] + b0, acc[mi][f][3] + b1);
        }
    }
}

// ---------------- phase 2: persistent LSTM recurrence ----------------
// 128 CTAs: ms = blk>>6 (B half, 64 rows), ns = blk&63 (16 h-cols -> 64 gate rows).
// SMEM: Whs 64x1032 halves (132096B) | Hs 4 buffers x 64x136 halves (17408B each).
// The fp32 gate-transpose buffer Gs ALIASES Hs buf0 (free after the MMA loop;
// reuse distance of buf0 is chunk 4, all threads are past chunk 6 when Gs is written).
#define WHS_STRIDE 1032
#define HCH_STRIDE 136
#define GS_STRIDE  68
#define HBUF_BYTES (64 * HCH_STRIDE * 2) /* 17408 */
#define P2_SMEM (132096 + 4 * HBUF_BYTES) /* 201728 B -> 1 CTA/SM */

__global__ void __launch_bounds__(256, 1) lstm_rec() {
    extern __shared__ unsigned char smraw[];
    __half* Whs = (__half*)smraw;
    __half* Hs  = (__half*)(smraw + 132096);
    float*  Gs  = (float*)(smraw + 132096);      // aliases Hs buf0
    const int tid = threadIdx.x;
    const int lane = tid & 31, wid = tid >> 5;
    const int wm = wid >> 2, wn = wid & 3;       // 2(M) x 4(N) warps
    const int ms = blockIdx.x >> 6;
    const int ns = blockIdx.x & 63;

    // Load resident Wh slice: smem row j -> gate (j>>4), h-col ns*16+(j&15)
#pragma unroll 4
    for (int it = 0; it < 32; ++it) {
        int task = tid + it * 256;
        int j = task >> 7, seg = task & 127;
        int grow = (j >> 4) * HH + ns * 16 + (j & 15);
        cp_async16(&Whs[j * WHS_STRIDE + seg * 8], g_Wh_h + (size_t)grow * HH + seg * 8);
    }
    cp_commit();
    cp_wait<0>();
    __syncthreads();

    float cst[4] = {0.f, 0.f, 0.f, 0.f};
    const int hc = tid & 15;
    const int brow0 = tid >> 4;   // 0..15 (+16k)

#define H_LOAD(buf, kc)                                                            \
    {                                                                              \
        _Pragma("unroll") for (int it = 0; it < 4; ++it) {                         \
            int task = tid + it * 256;                                             \
            int row = task >> 4, seg = task & 15;                                  \
            cp_async16(&Hs[(buf) * (64 * HCH_STRIDE) + row * HCH_STRIDE + seg * 8],\
                       hsrc + (size_t)row * HH + (kc) * 128 + seg * 8);            \
        }                                                                          \
    }

    for (int t = 0; t < SS; ++t) {
        const int par = t & 1;
        const __half* hsrc = g_h16[par] + (size_t)(ms * 64) * HH;

        // prefetch xg for this step (DRAM latency hidden under the MMA loop)
        __half xh[4][4];
        const __half* xgp = g_xg + ((size_t)t * BB + ms * 64) * GG + ns * 16 + hc;
#pragma unroll
        for (int k = 0; k < 4; ++k) {
            int b = brow0 + k * 16;
#pragma unroll
            for (int g = 0; g < 4; ++g) xh[k][g] = xgp[(size_t)b * GG + g * HH];
        }

        float acc[2][2][4];
#pragma unroll
        for (int mi = 0; mi < 2; ++mi)
#pragma unroll
            for (int nh = 0; nh < 2; ++nh)
#pragma unroll
                for (int u = 0; u < 4; ++u) acc[mi][nh][u] = 0.f;

        // 4-deep cp.async pipeline over the 8 k-chunks (prefetch 3 ahead)
        H_LOAD(0, 0); cp_commit();
        H_LOAD(1, 1); cp_commit();
        H_LOAD(2, 2); cp_commit();
#pragma unroll 1
        for (int kc = 0; kc < 8; ++kc) {
            if (kc < 6)      cp_wait<2>();
            else if (kc == 6) cp_wait<1>();
            else             cp_wait<0>();
            __syncthreads();
            if (kc < 5) { H_LOAD((kc + 3) & 3, kc + 3); cp_commit(); }
            const int buf = kc & 3;
#pragma unroll
            for (int kk = 0; kk < 8; ++kk) {
                uint32_t a[2][4];
#pragma unroll
                for (int mi = 0; mi < 2; ++mi)
                    ldsm_x4(a[mi], &Hs[buf * (64 * HCH_STRIDE) +
                                       (wm * 32 + mi * 16 + (lane & 15)) * HCH_STRIDE +
                                       kk * 16 + (lane >> 4) * 8]);
                uint32_t b4[4];
                ldsm_x4(b4, &Whs[(wn * 16 + (lane & 15)) * WHS_STRIDE +
                                 kc * 128 + kk * 16 + (lane >> 4) * 8]);
#pragma unroll
                for (int mi = 0; mi < 2; ++mi) {
                    mma16816(acc[mi][0], a[mi], b4[0], b4[2]);
                    mma16816(acc[mi][1], a[mi], b4[1], b4[3]);
                }
            }
        }

        // store gate tile to smem (transpose to per-(b,hc) access); Gs aliases Hs buf0
        {
            int r = lane >> 2, c2 = (lane & 3) * 2;
#pragma unroll
            for (int mi = 0; mi < 2; ++mi)
#pragma unroll
                for (int nh = 0; nh < 2; ++nh) {
                    int col = wn * 16 + nh * 8 + c2;
                    int row = wm * 32 + mi * 16 + r;
                    Gs[row * GS_STRIDE + col]           = acc[mi][nh][0];
                    Gs[row * GS_STRIDE + col + 1]       = acc[mi][nh][1];
                    Gs[(row + 8) * GS_STRIDE + col]     = acc[mi][nh][2];
                    Gs[(row + 8) * GS_STRIDE + col + 1] = acc[mi][nh][3];
                }
        }
        __syncthreads();

        // elementwise update; c in registers; write h fp16 to other buffer
        __half* hdst = g_h16[par ^ 1] + (size_t)(ms * 64) * HH + ns * 16;
#pragma unroll
        for (int k = 0; k < 4; ++k) {
            int b = brow0 + k * 16;
            float f  = Gs[b * GS_STRIDE + hc]      + __half2float(xh[k][0]);
            float i_ = Gs[b * GS_STRIDE + 16 + hc] + __half2float(xh[k][1]);
            float g  = Gs[b * GS_STRIDE + 32 + hc] + __half2float(xh[k][2]);
            float o  = Gs[b * GS_STRIDE + 48 + hc] + __half2float(xh[k][3]);
            cst[k] = sigm(f) * cst[k] + sigm(i_) * tanh_fast(g);
            float h = sigm(o) * tanh_fast(cst[k]);
            hdst[(size_t)b * HH + hc] = __float2half(h);
            if (t == SS - 1) g_h32[(size_t)(ms * 64 + b) * HH + ns * 16 + hc] = h;
        }
        grid_barrier();
    }
}

// ---------------- head: out = hT @ fc_w^T + fc_b  [128x128, K=1024] ----------------
__global__ void lstm_head(const float* __restrict__ fc_w, const float* __restrict__ fc_b,
                          float* __restrict__ out) {
    __shared__ float hrow[HH];
    int b = blockIdx.x;
    for (int i = threadIdx.x; i < HH; i += 128) hrow[i] = g_h32[(size_t)b * HH + i];
    __syncthreads();
    int o = threadIdx.x;
    const float4* wp = (const float4*)(fc_w + (size_t)o * HH);
    float s = 0.f;
#pragma unroll 4
    for (int i = 0; i < HH / 4; ++i) {
        float4 w = wp[i];
        s += w.x * hrow[i * 4] + w.y * hrow[i * 4 + 1] + w.z * hrow[i * 4 + 2] + w.w * hrow[i * 4 + 3];
    }
    out[b * 128 + o] = s + fc_b[o];
}

// ---------------- launch (5 launches; lstm_rec is #4 -> captured by ncu -s 5 -c 1) -------------
extern "C" void kernel_launch(void* const* d_in, const int* in_sizes, int n_in,
                              void* d_out, int out_size) {
    const float* x    = (const float*)d_in[0];
    const float* Wx   = (const float*)d_in[1];
    const float* bW   = (const float*)d_in[2];
    const float* Wh   = (const float*)d_in[3];
    const float* bU   = (const float*)d_in[4];
    const float* fc_w = (const float*)d_in[5];
    const float* fc_b = (const float*)d_in[6];
    float* out = (float*)d_out;

    cudaFuncSetAttribute(lstm_xproj, cudaFuncAttributeMaxDynamicSharedMemorySize, P1_SMEM);
    cudaFuncSetAttribute(lstm_rec,   cudaFuncAttributeMaxDynamicSharedMemorySize, P2_SMEM);

    lstm_prep_w<<<2048, 256>>>(Wx, Wh, bW, bU);
    lstm_prep_x<<<4096, 256>>>(x);
    lstm_xproj<<<dim3(32, 1024), 256, P1_SMEM>>>();
    lstm_rec<<<NCTA2, 256, P2_SMEM>>>();
    lstm_head<<<128, 128>>>(fc_w, fc_b, out);
}